// round 8
// baseline (speedup 1.0000x reference)
#include <cuda_runtime.h>
#include <cuda_bf16.h>

#define Bq 2
#define Sq 2048
#define Dm 1024
#define Hh 16
#define DKq 64
#define NROWS (Bq*Sq)      // 4096
#define BH (Bq*Hh)         // 32

typedef __nv_bfloat16 bf16;

// -------- device scratch (allocation-free rule: __device__ globals) ---------
__device__ bf16 g_xh[NROWS*Dm], g_xl[NROWS*Dm];
__device__ bf16 g_wh[4*Dm*Dm],  g_wl[4*Dm*Dm];
__device__ bf16 g_qh[BH*Sq*DKq], g_ql[BH*Sq*DKq];
__device__ bf16 g_kh[BH*Sq*DKq], g_kl[BH*Sq*DKq];
__device__ bf16 g_vh[BH*Sq*DKq], g_vl[BH*Sq*DKq];
__device__ bf16 g_ch[NROWS*Dm], g_cl[NROWS*Dm];
__device__ float g_invl[BH*Sq];         // per-row 1/sum

// ------------------------------- PTX helpers --------------------------------
#define LDSM4(r0,r1,r2,r3,addr) \
    asm volatile("ldmatrix.sync.aligned.m8n8.x4.shared.b16 {%0,%1,%2,%3},[%4];" \
                 : "=r"(r0),"=r"(r1),"=r"(r2),"=r"(r3) : "r"(addr))
#define LDSM4T(r0,r1,r2,r3,addr) \
    asm volatile("ldmatrix.sync.aligned.m8n8.x4.trans.shared.b16 {%0,%1,%2,%3},[%4];" \
                 : "=r"(r0),"=r"(r1),"=r"(r2),"=r"(r3) : "r"(addr))
#define MMA16816(ac,a,b) \
    asm volatile("mma.sync.aligned.m16n8k16.row.col.f32.bf16.bf16.f32 " \
                 "{%0,%1,%2,%3},{%4,%5,%6,%7},{%8,%9},{%0,%1,%2,%3};" \
                 : "+f"((ac)[0]),"+f"((ac)[1]),"+f"((ac)[2]),"+f"((ac)[3]) \
                 : "r"((a)[0]),"r"((a)[1]),"r"((a)[2]),"r"((a)[3]), \
                   "r"((b)[0]),"r"((b)[1]))
#define CPASYNC16(dst,src) \
    asm volatile("cp.async.cg.shared.global [%0],[%1],16;" \
                 :: "r"(dst), "l"(__cvta_generic_to_global((const void*)(src))))
#define CPCOMMIT asm volatile("cp.async.commit_group;")
#define CPWAIT0  asm volatile("cp.async.wait_group 0;")

__device__ __forceinline__ unsigned smaddr(const void* p) {
    return (unsigned)__cvta_generic_to_shared(p);
}

__device__ __forceinline__ float ex2(float x) {
    float r;
    asm("ex2.approx.f32 %0, %1;" : "=f"(r) : "f"(x));
    return r;
}

__device__ __forceinline__ unsigned pack_bf16x2(float hi, float lo) {
    unsigned r;
    asm("cvt.rn.bf16x2.f32 %0, %1, %2;" : "=r"(r) : "f"(hi), "f"(lo));
    return r;
}

__device__ __forceinline__ void split2(float x, float y, bf16* hp, bf16* lp) {
    unsigned h = pack_bf16x2(y, x);
    float rx = x - __uint_as_float(h << 16);
    float ry = y - __uint_as_float(h & 0xffff0000u);
    unsigned l = pack_bf16x2(ry, rx);
    *(unsigned*)hp = h;
    *(unsigned*)lp = l;
}

// ------------------------------- split kernels ------------------------------
__global__ __launch_bounds__(256) void split_kernel(
    const float* __restrict__ src, bf16* __restrict__ hi, bf16* __restrict__ lo, int n4)
{
    int i = blockIdx.x * blockDim.x + threadIdx.x;
    if (i >= n4) return;
    float4 v = ((const float4*)src)[i];
    split2(v.x, v.y, hi + (size_t)i*4,     lo + (size_t)i*4);
    split2(v.z, v.w, hi + (size_t)i*4 + 2, lo + (size_t)i*4 + 2);
}

__global__ __launch_bounds__(256) void wsplit_kernel(
    const float* __restrict__ w0, const float* __restrict__ w1,
    const float* __restrict__ w2, const float* __restrict__ w3,
    bf16* __restrict__ hi, bf16* __restrict__ lo)
{
    const int z = blockIdx.z;
    const float* src = (z == 0) ? w0 : (z == 1) ? w1 : (z == 2) ? w2 : w3;
    bf16* h = hi + (size_t)z * Dm * Dm;
    bf16* l = lo + (size_t)z * Dm * Dm;
    int i = blockIdx.x * blockDim.x + threadIdx.x;
    if (i >= Dm*Dm/4) return;
    float4 v = ((const float4*)src)[i];
    split2(v.x, v.y, h + (size_t)i*4,     l + (size_t)i*4);
    split2(v.z, v.w, h + (size_t)i*4 + 2, l + (size_t)i*4 + 2);
}

// ---------------------------------------------------------------------------
// NT GEMM on hi/lo bf16 pairs, occupancy-2 tiling:
// block = 128(M) x 64(N), 256 threads, 8 warps (4m x 2n), warp tile 32x32.
// K-tile 32, double-buffered cp.async. grid.z selects weight/bias/output set.
// mode 0: head-split bf16 hi/lo out (scaled). mode 1: fp32 rows out.
// ---------------------------------------------------------------------------
#define NT2_AH 0
#define NT2_AL 10240
#define NT2_WH 20480
#define NT2_WL 25600
#define NT2_STAGE_B 30720   // bytes per stage

__device__ __forceinline__ void nt2_load(
    unsigned sb,
    const bf16* __restrict__ Ah, const bf16* __restrict__ Al,
    const bf16* __restrict__ Wh, const bf16* __restrict__ Wl,
    int m0, int n0, int kt, int t)
{
#pragma unroll
    for (int j = 0; j < 2; j++) {              // A: 128 rows x 32 halves
        int idx = t + j*256;
        int row = idx >> 2;
        int q   = (idx & 3) * 8;
        unsigned so = (unsigned)(row*40 + q) * 2;
        CPASYNC16(sb + NT2_AH + so, Ah + (size_t)(m0+row)*Dm + kt + q);
        CPASYNC16(sb + NT2_AL + so, Al + (size_t)(m0+row)*Dm + kt + q);
    }
    {                                           // W: 64 rows x 32 halves
        int row = t >> 2;
        int q   = (t & 3) * 8;
        unsigned so = (unsigned)(row*40 + q) * 2;
        CPASYNC16(sb + NT2_WH + so, Wh + (size_t)(n0+row)*Dm + kt + q);
        CPASYNC16(sb + NT2_WL + so, Wl + (size_t)(n0+row)*Dm + kt + q);
    }
}

__global__ __launch_bounds__(256, 2) void gemm_bf16x2_nt(
    const bf16* __restrict__ Ah, const bf16* __restrict__ Al,
    const bf16* __restrict__ WhB, const bf16* __restrict__ WlB,
    const float* __restrict__ b0, const float* __restrict__ b1,
    const float* __restrict__ b2, float qscale,
    bf16* __restrict__ o0h, bf16* __restrict__ o0l,
    bf16* __restrict__ o1h, bf16* __restrict__ o1l,
    bf16* __restrict__ o2h, bf16* __restrict__ o2l,
    float* __restrict__ outF, int mode)
{
    extern __shared__ bf16 sm[];
    const int t    = threadIdx.x;
    const int lane = t & 31;
    const int wid  = t >> 5;
    const int warp_m = wid >> 1;    // 0..3 (x32 rows)
    const int warp_n = wid & 1;     // 0..1 (x32 cols)
    const int m0 = blockIdx.y * 128;
    const int n0 = blockIdx.x * 64;
    const int z  = blockIdx.z;

    const bf16* Wh = WhB + (size_t)z * Dm * Dm;
    const bf16* Wl = WlB + (size_t)z * Dm * Dm;
    const float* bias = (z == 0) ? b0 : (z == 1 ? b1 : b2);
    const float scale = (mode == 0 && z == 0) ? qscale : 1.f;

    float acc[2][4][4];
#pragma unroll
    for (int i = 0; i < 2; i++)
#pragma unroll
        for (int j = 0; j < 4; j++)
#pragma unroll
            for (int r = 0; r < 4; r++) acc[i][j][r] = 0.f;

    const unsigned s0 = smaddr(sm);
    const int nk = Dm / 32;     // 32

    nt2_load(s0, Ah, Al, Wh, Wl, m0, n0, 0, t);
    CPCOMMIT;

    for (int i = 0; i < nk; i++) {
        CPWAIT0;
        __syncthreads();
        if (i + 1 < nk) {
            nt2_load(s0 + ((i+1)&1)*NT2_STAGE_B, Ah, Al, Wh, Wl,
                     m0, n0, (i+1)*32, t);
            CPCOMMIT;
        }
        unsigned sb = s0 + (i&1)*NT2_STAGE_B;

#pragma unroll
        for (int k16 = 0; k16 < 32; k16 += 16) {
            unsigned ah[2][4], al[2][4], bh[4][2], bl[4][2];
            int arow = warp_m*32 + (lane & 15);
            int acol = k16 + ((lane >> 4) << 3);
#pragma unroll
            for (int mt = 0; mt < 2; mt++) {
                unsigned ad = sb + (unsigned)((arow + mt*16)*40 + acol)*2;
                LDSM4(ah[mt][0], ah[mt][1], ah[mt][2], ah[mt][3], ad + NT2_AH);
                LDSM4(al[mt][0], al[mt][1], al[mt][2], al[mt][3], ad + NT2_AL);
            }
            int brow = warp_n*32 + ((lane >> 4) << 3) + (lane & 7);
            int bcol = k16 + (((lane >> 3) & 1) << 3);
#pragma unroll
            for (int pr = 0; pr < 2; pr++) {
                unsigned bd = sb + (unsigned)((brow + pr*16)*40 + bcol)*2;
                unsigned r0, r1, r2, r3;
                LDSM4(r0, r1, r2, r3, bd + NT2_WH);
                bh[pr*2][0] = r0; bh[pr*2][1] = r1;
                bh[pr*2+1][0] = r2; bh[pr*2+1][1] = r3;
                LDSM4(r0, r1, r2, r3, bd + NT2_WL);
                bl[pr*2][0] = r0; bl[pr*2][1] = r1;
                bl[pr*2+1][0] = r2; bl[pr*2+1][1] = r3;
            }
#pragma unroll
            for (int mt = 0; mt < 2; mt++)
#pragma unroll
                for (int nt = 0; nt < 4; nt++) {
                    MMA16816(acc[mt][nt], ah[mt], bh[nt]);
                    MMA16816(acc[mt][nt], ah[mt], bl[nt]);
                    MMA16816(acc[mt][nt], al[mt], bh[nt]);
                }
        }
    }

#pragma unroll
    for (int mt = 0; mt < 2; mt++)
#pragma unroll
        for (int nt = 0; nt < 4; nt++) {
            int r = m0 + warp_m*32 + mt*16 + (lane >> 2);
            int c = n0 + warp_n*32 + nt*8 + ((lane & 3) << 1);
            float v00 = acc[mt][nt][0] + bias[c];
            float v01 = acc[mt][nt][1] + bias[c+1];
            float v10 = acc[mt][nt][2] + bias[c];
            float v11 = acc[mt][nt][3] + bias[c+1];
            if (mode == 1) {
                *(float2*)&outF[(size_t)r*Dm + c]     = make_float2(v00, v01);
                *(float2*)&outF[(size_t)(r+8)*Dm + c] = make_float2(v10, v11);
            } else {
                v00 *= scale; v01 *= scale; v10 *= scale; v11 *= scale;
                bf16* ohp = (z == 0) ? o0h : (z == 1 ? o1h : o2h);
                bf16* olp = (z == 0) ? o0l : (z == 1 ? o1l : o2l);
                int b = r >> 11, s = r & 2047;
                int h = c >> 6,  dk = c & 63;
                size_t base = (((size_t)(b*Hh + h))*Sq + s)*DKq + dk;
                split2(v00, v01, ohp + base, olp + base);
                split2(v10, v11, ohp + base + 8*DKq, olp + base + 8*DKq);
            }
        }
}

// ---------------------------------------------------------------------------
// Fused attention (single pass over K/V) — unchanged from R6.
// ---------------------------------------------------------------------------
#define KT 64
#define KV_BUF_H 9216
#define Q_H 9216

__device__ __forceinline__ void load_kv_tile(
    unsigned dsth, const bf16* __restrict__ gh, const bf16* __restrict__ gl,
    int row0, int t)
{
#pragma unroll
    for (int j = 0; j < 2; j++) {
        int c = t + j*256;
        int row = c >> 3, q = (c & 7)*8;
        unsigned so = (unsigned)(row*72 + q)*2;
        CPASYNC16(dsth + so,          gh + (size_t)(row0+row)*DKq + q);
        CPASYNC16(dsth + 4608*2 + so, gl + (size_t)(row0+row)*DKq + q);
    }
}

__device__ __forceinline__ void compute_s(
    float s[8][4], const unsigned qfh[4][4], const unsigned qfl[4][4],
    unsigned kbuf, int lane)
{
#pragma unroll
    for (int j = 0; j < 8; j++)
#pragma unroll
        for (int r = 0; r < 4; r++) s[j][r] = 0.f;

    const int rbase = ((lane >> 4) << 3) + (lane & 7);
#pragma unroll
    for (int f = 0; f < 4; f++) {
        const int cbase = f*16 + (((lane >> 3) & 1) << 3);
#pragma unroll
        for (int pr = 0; pr < 4; pr++) {
            unsigned off = (unsigned)((pr*16 + rbase)*72 + cbase)*2;
            unsigned h0,h1,h2,h3, l0,l1,l2,l3;
            LDSM4(h0,h1,h2,h3, kbuf + off);
            LDSM4(l0,l1,l2,l3, kbuf + 4608*2 + off);
            unsigned bh0[2]={h0,h1}, bh1[2]={h2,h3};
            unsigned bl0[2]={l0,l1}, bl1[2]={l2,l3};
            MMA16816(s[2*pr],   qfh[f], bh0);
            MMA16816(s[2*pr],   qfh[f], bl0);
            MMA16816(s[2*pr],   qfl[f], bh0);
            MMA16816(s[2*pr+1], qfh[f], bh1);
            MMA16816(s[2*pr+1], qfh[f], bl1);
            MMA16816(s[2*pr+1], qfl[f], bh1);
        }
    }
}

__global__ __launch_bounds__(256) void attn_fused(
    const bf16* __restrict__ qh_g, const bf16* __restrict__ ql_g,
    const bf16* __restrict__ kh_g, const bf16* __restrict__ kl_g,
    const bf16* __restrict__ vh_g, const bf16* __restrict__ vl_g,
    float* __restrict__ attn, float* __restrict__ invl,
    bf16* __restrict__ ctxh, bf16* __restrict__ ctxl)
{
    extern __shared__ bf16 smb[];
    const int t = threadIdx.x, lane = t & 31, warp = t >> 5;
    const int bh = blockIdx.y, q0 = blockIdx.x * 128;
    const bf16* Qh = qh_g + (size_t)bh*Sq*DKq;
    const bf16* Ql = ql_g + (size_t)bh*Sq*DKq;
    const bf16* Kh = kh_g + (size_t)bh*Sq*DKq;
    const bf16* Kl = kl_g + (size_t)bh*Sq*DKq;
    const bf16* Vh = vh_g + (size_t)bh*Sq*DKq;
    const bf16* Vl = vl_g + (size_t)bh*Sq*DKq;

    const unsigned s0 = smaddr(smb);
    const unsigned qb = s0;
    const unsigned kb = s0 + 2*Q_H*2;
    const unsigned vb = kb + 2*KV_BUF_H*2;

#pragma unroll
    for (int j = 0; j < 4; j++) {
        int c = t + j*256;
        int row = c >> 3, q = (c & 7)*8;
        unsigned so = (unsigned)(row*72 + q)*2;
        CPASYNC16(qb + so,         Qh + (size_t)(q0+row)*DKq + q);
        CPASYNC16(qb + Q_H*2 + so, Ql + (size_t)(q0+row)*DKq + q);
    }
    load_kv_tile(kb, Kh, Kl, 0, t);
    load_kv_tile(vb, Vh, Vl, 0, t);
    CPCOMMIT;
    CPWAIT0;
    __syncthreads();

    unsigned qfh[4][4], qfl[4][4];
    {
        int arow = warp*16 + (lane & 15);
#pragma unroll
        for (int f = 0; f < 4; f++) {
            unsigned ad = qb + (unsigned)(arow*72 + f*16 + ((lane >> 4) << 3))*2;
            LDSM4(qfh[f][0], qfh[f][1], qfh[f][2], qfh[f][3], ad);
            LDSM4(qfl[f][0], qfl[f][1], qfl[f][2], qfl[f][3], ad + Q_H*2);
        }
    }

    const int g = lane >> 2;
    const int r0 = q0 + warp*16 + g;
    float* aptr0 = attn + ((size_t)bh*Sq + r0)*Sq + 2*(lane & 3);
    float* aptr1 = aptr0 + (size_t)8*Sq;

    float ctx[8][4];
#pragma unroll
    for (int j = 0; j < 8; j++)
#pragma unroll
        for (int r = 0; r < 4; r++) ctx[j][r] = 0.f;

    float l0v = 0.f, l1v = 0.f;
    const int nk = Sq / KT;

    for (int i = 0; i < nk; i++) {
        if (i > 0) { CPWAIT0; __syncthreads(); }
        if (i + 1 < nk) {
            load_kv_tile(kb + ((i+1)&1)*KV_BUF_H*2, Kh, Kl, (i+1)*KT, t);
            load_kv_tile(vb + ((i+1)&1)*KV_BUF_H*2, Vh, Vl, (i+1)*KT, t);
            CPCOMMIT;
        }
        float s[8][4];
        compute_s(s, qfh, qfl, kb + (i&1)*KV_BUF_H*2, lane);

        const int k0 = i*KT;
#pragma unroll
        for (int j = 0; j < 8; j++) {
            float p0 = ex2(s[j][0]);
            float p1 = ex2(s[j][1]);
            float p2 = ex2(s[j][2]);
            float p3 = ex2(s[j][3]);
            *(float2*)(aptr0 + k0 + 8*j) = make_float2(p0, p1);
            *(float2*)(aptr1 + k0 + 8*j) = make_float2(p2, p3);
            l0v += p0 + p1;
            l1v += p2 + p3;
            s[j][0] = p0; s[j][1] = p1; s[j][2] = p2; s[j][3] = p3;
        }

        const unsigned vbuf = vb + (i&1)*KV_BUF_H*2;
#pragma unroll
        for (int f = 0; f < 4; f++) {
            unsigned pah[4], pal[4];
#pragma unroll
            for (int u = 0; u < 2; u++) {
                const float* pv = s[2*f + u];
                unsigned h0 = pack_bf16x2(pv[1], pv[0]);
                float e0 = pv[0] - __uint_as_float(h0 << 16);
                float e1 = pv[1] - __uint_as_float(h0 & 0xffff0000u);
                pal[2*u]   = pack_bf16x2(e1, e0);
                pah[2*u]   = h0;
                unsigned h1 = pack_bf16x2(pv[3], pv[2]);
                float e2 = pv[2] - __uint_as_float(h1 << 16);
                float e3 = pv[3] - __uint_as_float(h1 & 0xffff0000u);
                pal[2*u+1] = pack_bf16x2(e3, e2);
                pah[2*u+1] = h1;
            }
            unsigned pahf[4] = {pah[0], pah[1], pah[2], pah[3]};
            unsigned palf[4] = {pal[0], pal[1], pal[2], pal[3]};

#pragma unroll
            for (int pr = 0; pr < 4; pr++) {
                unsigned off = (unsigned)((f*16 + (lane & 15))*72
                               + pr*16 + ((lane >> 4) << 3))*2;
                unsigned h0,h1,h2,h3, l0,l1,l2,l3;
                LDSM4T(h0,h1,h2,h3, vbuf + off);
                LDSM4T(l0,l1,l2,l3, vbuf + 4608*2 + off);
                unsigned bh0[2]={h0,h1}, bh1[2]={h2,h3};
                unsigned bl0[2]={l0,l1}, bl1[2]={l2,l3};
                MMA16816(ctx[2*pr],   pahf, bh0);
                MMA16816(ctx[2*pr],   pahf, bl0);
                MMA16816(ctx[2*pr],   palf, bh0);
                MMA16816(ctx[2*pr+1], pahf, bh1);
                MMA16816(ctx[2*pr+1], pahf, bl1);
                MMA16816(ctx[2*pr+1], palf, bh1);
            }
        }
        __syncthreads();
    }

    l0v += __shfl_xor_sync(0xffffffffu, l0v, 1);
    l0v += __shfl_xor_sync(0xffffffffu, l0v, 2);
    l1v += __shfl_xor_sync(0xffffffffu, l1v, 1);
    l1v += __shfl_xor_sync(0xffffffffu, l1v, 2);
    const float il0 = 1.0f / l0v;
    const float il1 = 1.0f / l1v;

    if ((lane & 3) == 0) {
        invl[(size_t)bh*Sq + r0]     = il0;
        invl[(size_t)bh*Sq + r0 + 8] = il1;
    }

    const int b = bh >> 4, hidx = bh & 15;
#pragma unroll
    for (int j = 0; j < 8; j++) {
        int d = hidx*DKq + 8*j + 2*(lane & 3);
        size_t idx0 = ((size_t)(b*Sq + r0))*Dm + d;
        split2(ctx[j][0]*il0, ctx[j][1]*il0, ctxh + idx0, ctxl + idx0);
        size_t idx1 = idx0 + (size_t)8*Dm;
        split2(ctx[j][2]*il1, ctx[j][3]*il1, ctxh + idx1, ctxl + idx1);
    }
}

// ---------------------------------------------------------------------------
// fixup: attn[row][:] *= invl[row]
// ---------------------------------------------------------------------------
__global__ __launch_bounds__(256) void fixup_kernel(
    float* __restrict__ attn, const float* __restrict__ invl)
{
    const size_t row = blockIdx.x;
    const float s = invl[row];
    float4* p = (float4*)(attn + row * Sq);
    const int t = threadIdx.x;
    float4 a = p[t], b = p[t + 256];
    a.x *= s; a.y *= s; a.z *= s; a.w *= s;
    b.x *= s; b.y *= s; b.z *= s; b.w *= s;
    p[t] = a;
    p[t + 256] = b;
}

// ---------------------------------------------------------------------------
extern "C" void kernel_launch(void* const* d_in, const int* in_sizes, int n_in,
                              void* d_out, int out_size)
{
    const float* x  = (const float*)d_in[0];
    const float* Wq = (const float*)d_in[1];
    const float* bq = (const float*)d_in[2];
    const float* Wk = (const float*)d_in[3];
    const float* bk = (const float*)d_in[4];
    const float* Wv = (const float*)d_in[5];
    const float* bv = (const float*)d_in[6];
    const float* Wo = (const float*)d_in[7];
    const float* bo = (const float*)d_in[8];

    float* out  = (float*)d_out;
    float* attn = out + (size_t)NROWS * Dm;

    bf16 *xh, *xl, *wh, *wl, *qh, *ql, *kh, *kl, *vh, *vl, *ch, *cl;
    float* invl;
    cudaGetSymbolAddress((void**)&xh, g_xh); cudaGetSymbolAddress((void**)&xl, g_xl);
    cudaGetSymbolAddress((void**)&wh, g_wh); cudaGetSymbolAddress((void**)&wl, g_wl);
    cudaGetSymbolAddress((void**)&qh, g_qh); cudaGetSymbolAddress((void**)&ql, g_ql);
    cudaGetSymbolAddress((void**)&kh, g_kh); cudaGetSymbolAddress((void**)&kl, g_kl);
    cudaGetSymbolAddress((void**)&vh, g_vh); cudaGetSymbolAddress((void**)&vl, g_vl);
    cudaGetSymbolAddress((void**)&ch, g_ch); cudaGetSymbolAddress((void**)&cl, g_cl);
    cudaGetSymbolAddress((void**)&invl, g_invl);

    const int ntSmem = 2 * NT2_STAGE_B;              // 61440 B
    const int faSmem = (2*Q_H + 4*KV_BUF_H) * 2;     // 110592 B
    cudaFuncSetAttribute(gemm_bf16x2_nt, cudaFuncAttributeMaxDynamicSharedMemorySize, ntSmem);
    cudaFuncSetAttribute(attn_fused,     cudaFuncAttributeMaxDynamicSharedMemorySize, faSmem);

    // side stream + events (host-side ops, graph-capture safe)
    cudaStream_t s2;
    cudaStreamCreate(&s2);
    cudaEvent_t evF1, evJ1, evF2, evJ2;
    cudaEventCreateWithFlags(&evF1, cudaEventDisableTiming);
    cudaEventCreateWithFlags(&evJ1, cudaEventDisableTiming);
    cudaEventCreateWithFlags(&evF2, cudaEventDisableTiming);
    cudaEventCreateWithFlags(&evJ2, cudaEventDisableTiming);

    // ---- fork 1: W splits (s2) || x split (main) ----
    cudaEventRecord(evF1, 0);
    cudaStreamWaitEvent(s2, evF1, 0);

    const int wq4 = Dm*Dm/4;
    dim3 gW((wq4 + 255)/256, 1, 4);
    wsplit_kernel<<<gW, 256, 0, s2>>>(Wq, Wk, Wv, Wo, wh, wl);
    split_kernel<<<(NROWS*Dm/4 + 255)/256, 256>>>(x, xh, xl, NROWS*Dm/4);

    cudaEventRecord(evJ1, s2);
    cudaStreamWaitEvent(0, evJ1, 0);

    // ---- Q/K/V projections: single fused launch, z = 0/1/2 ----
    const float QSCALE = 0.18033688011112042f;  // log2(e)/8
    dim3 gQKV(Dm/64, NROWS/128, 3);              // (16, 32, 3) = 1536 blocks
    gemm_bf16x2_nt<<<gQKV, 256, ntSmem>>>(xh, xl, wh, wl, bq, bk, bv, QSCALE,
                                          qh, ql, kh, kl, vh, vl, nullptr, 0);

    // ---- fused attention ----
    dim3 gAttn(Sq/128, BH);   // (16, 32)
    attn_fused<<<gAttn, 256, faSmem>>>(qh, ql, kh, kl, vh, vl, attn, invl, ch, cl);

    // ---- fork 2: fixup (s2, DRAM-bound) || O-projection (main, tensor-bound) ----
    cudaEventRecord(evF2, 0);
    cudaStreamWaitEvent(s2, evF2, 0);

    fixup_kernel<<<BH*Sq, 256, 0, s2>>>(attn, invl);

    dim3 gO(Dm/64, NROWS/128, 1);
    gemm_bf16x2_nt<<<gO, 256, ntSmem>>>(ch, cl, wh + (size_t)3*Dm*Dm,
                                        wl + (size_t)3*Dm*Dm,
                                        bo, bo, bo, 1.f,
                                        nullptr, nullptr, nullptr, nullptr,
                                        nullptr, nullptr, out, 1);

    cudaEventRecord(evJ2, s2);
    cudaStreamWaitEvent(0, evJ2, 0);
}

// round 9
// speedup vs baseline: 1.0283x; 1.0283x over previous
#include <cuda_runtime.h>
#include <cuda_bf16.h>

#define Bq 2
#define Sq 2048
#define Dm 1024
#define Hh 16
#define DKq 64
#define NROWS (Bq*Sq)      // 4096
#define BH (Bq*Hh)         // 32

typedef __nv_bfloat16 bf16;

// -------- device scratch (allocation-free rule: __device__ globals) ---------
__device__ bf16 g_xh[NROWS*Dm], g_xl[NROWS*Dm];
__device__ bf16 g_wh[4*Dm*Dm],  g_wl[4*Dm*Dm];
__device__ bf16 g_qh[BH*Sq*DKq], g_ql[BH*Sq*DKq];
__device__ bf16 g_kh[BH*Sq*DKq], g_kl[BH*Sq*DKq];
__device__ bf16 g_vh[BH*Sq*DKq], g_vl[BH*Sq*DKq];
__device__ bf16 g_ch[NROWS*Dm], g_cl[NROWS*Dm];
__device__ float g_invl[BH*Sq];         // per-row 1/sum

// ------------------------------- PTX helpers --------------------------------
#define LDSM4(r0,r1,r2,r3,addr) \
    asm volatile("ldmatrix.sync.aligned.m8n8.x4.shared.b16 {%0,%1,%2,%3},[%4];" \
                 : "=r"(r0),"=r"(r1),"=r"(r2),"=r"(r3) : "r"(addr))
#define LDSM4T(r0,r1,r2,r3,addr) \
    asm volatile("ldmatrix.sync.aligned.m8n8.x4.trans.shared.b16 {%0,%1,%2,%3},[%4];" \
                 : "=r"(r0),"=r"(r1),"=r"(r2),"=r"(r3) : "r"(addr))
#define MMA16816(ac,a,b) \
    asm volatile("mma.sync.aligned.m16n8k16.row.col.f32.bf16.bf16.f32 " \
                 "{%0,%1,%2,%3},{%4,%5,%6,%7},{%8,%9},{%0,%1,%2,%3};" \
                 : "+f"((ac)[0]),"+f"((ac)[1]),"+f"((ac)[2]),"+f"((ac)[3]) \
                 : "r"((a)[0]),"r"((a)[1]),"r"((a)[2]),"r"((a)[3]), \
                   "r"((b)[0]),"r"((b)[1]))
#define CPASYNC16(dst,src) \
    asm volatile("cp.async.cg.shared.global [%0],[%1],16;" \
                 :: "r"(dst), "l"(__cvta_generic_to_global((const void*)(src))))
#define CPCOMMIT asm volatile("cp.async.commit_group;")
#define CPWAIT0  asm volatile("cp.async.wait_group 0;")

__device__ __forceinline__ unsigned smaddr(const void* p) {
    return (unsigned)__cvta_generic_to_shared(p);
}

__device__ __forceinline__ float ex2(float x) {
    float r;
    asm("ex2.approx.f32 %0, %1;" : "=f"(r) : "f"(x));
    return r;
}

__device__ __forceinline__ unsigned pack_bf16x2(float hi, float lo) {
    unsigned r;
    asm("cvt.rn.bf16x2.f32 %0, %1, %2;" : "=r"(r) : "f"(hi), "f"(lo));
    return r;
}

__device__ __forceinline__ void split2(float x, float y, bf16* hp, bf16* lp) {
    unsigned h = pack_bf16x2(y, x);
    float rx = x - __uint_as_float(h << 16);
    float ry = y - __uint_as_float(h & 0xffff0000u);
    unsigned l = pack_bf16x2(ry, rx);
    *(unsigned*)hp = h;
    *(unsigned*)lp = l;
}

// ------------------------------- split kernels ------------------------------
__global__ __launch_bounds__(256) void split_kernel(
    const float* __restrict__ src, bf16* __restrict__ hi, bf16* __restrict__ lo, int n4)
{
    int i = blockIdx.x * blockDim.x + threadIdx.x;
    if (i >= n4) return;
    float4 v = ((const float4*)src)[i];
    split2(v.x, v.y, hi + (size_t)i*4,     lo + (size_t)i*4);
    split2(v.z, v.w, hi + (size_t)i*4 + 2, lo + (size_t)i*4 + 2);
}

__global__ __launch_bounds__(256) void wsplit_kernel(
    const float* __restrict__ w0, const float* __restrict__ w1,
    const float* __restrict__ w2, const float* __restrict__ w3,
    bf16* __restrict__ hi, bf16* __restrict__ lo)
{
    const int z = blockIdx.z;
    const float* src = (z == 0) ? w0 : (z == 1) ? w1 : (z == 2) ? w2 : w3;
    bf16* h = hi + (size_t)z * Dm * Dm;
    bf16* l = lo + (size_t)z * Dm * Dm;
    int i = blockIdx.x * blockDim.x + threadIdx.x;
    if (i >= Dm*Dm/4) return;
    float4 v = ((const float4*)src)[i];
    split2(v.x, v.y, h + (size_t)i*4,     l + (size_t)i*4);
    split2(v.z, v.w, h + (size_t)i*4 + 2, l + (size_t)i*4 + 2);
}

// ---------------------------------------------------------------------------
// NT GEMM on hi/lo bf16 pairs: 128x128 block, 256 threads, 8 warps (2m x 4n),
// warp tile 64x32, K-tile 32, double-buffered cp.async. occupancy 2.
// grid.z selects weight/bias/output set.
// mode 0: head-split bf16 hi/lo out (z=0 scaled by qscale). mode 1: fp32 rows.
// ---------------------------------------------------------------------------
#define NT_STAGE_H 20480   // halves per stage: 4 matrices * 128*40

__device__ __forceinline__ void nt_load(
    unsigned sb,
    const bf16* __restrict__ Ah, const bf16* __restrict__ Al,
    const bf16* __restrict__ Wh, const bf16* __restrict__ Wl,
    int m0, int n0, int kt, int t)
{
#pragma unroll
    for (int j = 0; j < 2; j++) {
        int idx = t + j*256;
        int row = idx >> 2;
        int q   = (idx & 3) * 8;
        unsigned so = (unsigned)(row*40 + q) * 2;
        CPASYNC16(sb + so,               Ah + (size_t)(m0+row)*Dm + kt + q);
        CPASYNC16(sb + 5120*2  + so,     Al + (size_t)(m0+row)*Dm + kt + q);
        CPASYNC16(sb + 10240*2 + so,     Wh + (size_t)(n0+row)*Dm + kt + q);
        CPASYNC16(sb + 15360*2 + so,     Wl + (size_t)(n0+row)*Dm + kt + q);
    }
}

__global__ __launch_bounds__(256, 2) void gemm_bf16x2_nt(
    const bf16* __restrict__ Ah, const bf16* __restrict__ Al,
    const bf16* __restrict__ WhB, const bf16* __restrict__ WlB,
    const float* __restrict__ b0, const float* __restrict__ b1,
    const float* __restrict__ b2, float qscale,
    bf16* __restrict__ o0h, bf16* __restrict__ o0l,
    bf16* __restrict__ o1h, bf16* __restrict__ o1l,
    bf16* __restrict__ o2h, bf16* __restrict__ o2l,
    float* __restrict__ outF, int mode)
{
    extern __shared__ bf16 sm[];
    const int t    = threadIdx.x;
    const int lane = t & 31;
    const int wid  = t >> 5;
    const int warp_m = wid >> 2;    // 0..1 (x64)
    const int warp_n = wid & 3;     // 0..3 (x32)
    const int m0 = blockIdx.y * 128;
    const int n0 = blockIdx.x * 128;
    const int z  = blockIdx.z;

    const bf16* Wh = WhB + (size_t)z * Dm * Dm;
    const bf16* Wl = WlB + (size_t)z * Dm * Dm;
    const float* bias = (z == 0) ? b0 : (z == 1 ? b1 : b2);
    const float scale = (mode == 0 && z == 0) ? qscale : 1.f;

    float acc[4][4][4];
#pragma unroll
    for (int i = 0; i < 4; i++)
#pragma unroll
        for (int j = 0; j < 4; j++)
#pragma unroll
            for (int r = 0; r < 4; r++) acc[i][j][r] = 0.f;

    const unsigned s0 = smaddr(sm);
    const int nk = Dm / 32;    // 32

    nt_load(s0, Ah, Al, Wh, Wl, m0, n0, 0, t);
    CPCOMMIT;

    for (int i = 0; i < nk; i++) {
        CPWAIT0;
        __syncthreads();
        if (i + 1 < nk) {
            nt_load(s0 + ((i+1)&1)*NT_STAGE_H*2, Ah, Al, Wh, Wl,
                    m0, n0, (i+1)*32, t);
            CPCOMMIT;
        }
        unsigned sb = s0 + (i&1)*NT_STAGE_H*2;

#pragma unroll
        for (int k16 = 0; k16 < 32; k16 += 16) {
            unsigned ah[4][4], al[4][4], bh[4][2], bl[4][2];
            int arow = warp_m*64 + (lane & 15);
            int acol = k16 + ((lane >> 4) << 3);
#pragma unroll
            for (int mt = 0; mt < 4; mt++) {
                unsigned ad = sb + (unsigned)((arow + mt*16)*40 + acol)*2;
                LDSM4(ah[mt][0], ah[mt][1], ah[mt][2], ah[mt][3], ad);
                LDSM4(al[mt][0], al[mt][1], al[mt][2], al[mt][3], ad + 5120*2);
            }
            int brow = warp_n*32 + ((lane >> 4) << 3) + (lane & 7);
            int bcol = k16 + (((lane >> 3) & 1) << 3);
#pragma unroll
            for (int pr = 0; pr < 2; pr++) {
                unsigned bd = sb + 10240*2 + (unsigned)((brow + pr*16)*40 + bcol)*2;
                unsigned r0, r1, r2, r3;
                LDSM4(r0, r1, r2, r3, bd);
                bh[pr*2][0] = r0; bh[pr*2][1] = r1;
                bh[pr*2+1][0] = r2; bh[pr*2+1][1] = r3;
                LDSM4(r0, r1, r2, r3, bd + 5120*2);
                bl[pr*2][0] = r0; bl[pr*2][1] = r1;
                bl[pr*2+1][0] = r2; bl[pr*2+1][1] = r3;
            }
#pragma unroll
            for (int mt = 0; mt < 4; mt++)
#pragma unroll
                for (int nt = 0; nt < 4; nt++) {
                    MMA16816(acc[mt][nt], ah[mt], bh[nt]);
                    MMA16816(acc[mt][nt], ah[mt], bl[nt]);
                    MMA16816(acc[mt][nt], al[mt], bh[nt]);
                }
        }
    }

#pragma unroll
    for (int mt = 0; mt < 4; mt++)
#pragma unroll
        for (int nt = 0; nt < 4; nt++) {
            int r = m0 + warp_m*64 + mt*16 + (lane >> 2);
            int c = n0 + warp_n*32 + nt*8 + ((lane & 3) << 1);
            float v00 = acc[mt][nt][0] + bias[c];
            float v01 = acc[mt][nt][1] + bias[c+1];
            float v10 = acc[mt][nt][2] + bias[c];
            float v11 = acc[mt][nt][3] + bias[c+1];
            if (mode == 1) {
                *(float2*)&outF[(size_t)r*Dm + c]     = make_float2(v00, v01);
                *(float2*)&outF[(size_t)(r+8)*Dm + c] = make_float2(v10, v11);
            } else {
                v00 *= scale; v01 *= scale; v10 *= scale; v11 *= scale;
                bf16* ohp = (z == 0) ? o0h : (z == 1 ? o1h : o2h);
                bf16* olp = (z == 0) ? o0l : (z == 1 ? o1l : o2l);
                int b = r >> 11, s = r & 2047;
                int h = c >> 6,  dk = c & 63;
                size_t base = (((size_t)(b*Hh + h))*Sq + s)*DKq + dk;
                split2(v00, v01, ohp + base, olp + base);
                split2(v10, v11, ohp + base + 8*DKq, olp + base + 8*DKq);
            }
        }
}

// ---------------------------------------------------------------------------
// Fused attention (single pass over K/V) — unchanged from the 803us version.
// ---------------------------------------------------------------------------
#define KT 64
#define KV_BUF_H 9216
#define Q_H 9216

__device__ __forceinline__ void load_kv_tile(
    unsigned dsth, const bf16* __restrict__ gh, const bf16* __restrict__ gl,
    int row0, int t)
{
#pragma unroll
    for (int j = 0; j < 2; j++) {
        int c = t + j*256;
        int row = c >> 3, q = (c & 7)*8;
        unsigned so = (unsigned)(row*72 + q)*2;
        CPASYNC16(dsth + so,          gh + (size_t)(row0+row)*DKq + q);
        CPASYNC16(dsth + 4608*2 + so, gl + (size_t)(row0+row)*DKq + q);
    }
}

__device__ __forceinline__ void compute_s(
    float s[8][4], const unsigned qfh[4][4], const unsigned qfl[4][4],
    unsigned kbuf, int lane)
{
#pragma unroll
    for (int j = 0; j < 8; j++)
#pragma unroll
        for (int r = 0; r < 4; r++) s[j][r] = 0.f;

    const int rbase = ((lane >> 4) << 3) + (lane & 7);
#pragma unroll
    for (int f = 0; f < 4; f++) {
        const int cbase = f*16 + (((lane >> 3) & 1) << 3);
#pragma unroll
        for (int pr = 0; pr < 4; pr++) {
            unsigned off = (unsigned)((pr*16 + rbase)*72 + cbase)*2;
            unsigned h0,h1,h2,h3, l0,l1,l2,l3;
            LDSM4(h0,h1,h2,h3, kbuf + off);
            LDSM4(l0,l1,l2,l3, kbuf + 4608*2 + off);
            unsigned bh0[2]={h0,h1}, bh1[2]={h2,h3};
            unsigned bl0[2]={l0,l1}, bl1[2]={l2,l3};
            MMA16816(s[2*pr],   qfh[f], bh0);
            MMA16816(s[2*pr],   qfh[f], bl0);
            MMA16816(s[2*pr],   qfl[f], bh0);
            MMA16816(s[2*pr+1], qfh[f], bh1);
            MMA16816(s[2*pr+1], qfh[f], bl1);
            MMA16816(s[2*pr+1], qfl[f], bh1);
        }
    }
}

__global__ __launch_bounds__(256) void attn_fused(
    const bf16* __restrict__ qh_g, const bf16* __restrict__ ql_g,
    const bf16* __restrict__ kh_g, const bf16* __restrict__ kl_g,
    const bf16* __restrict__ vh_g, const bf16* __restrict__ vl_g,
    float* __restrict__ attn, float* __restrict__ invl,
    bf16* __restrict__ ctxh, bf16* __restrict__ ctxl)
{
    extern __shared__ bf16 smb[];
    const int t = threadIdx.x, lane = t & 31, warp = t >> 5;
    const int bh = blockIdx.y, q0 = blockIdx.x * 128;
    const bf16* Qh = qh_g + (size_t)bh*Sq*DKq;
    const bf16* Ql = ql_g + (size_t)bh*Sq*DKq;
    const bf16* Kh = kh_g + (size_t)bh*Sq*DKq;
    const bf16* Kl = kl_g + (size_t)bh*Sq*DKq;
    const bf16* Vh = vh_g + (size_t)bh*Sq*DKq;
    const bf16* Vl = vl_g + (size_t)bh*Sq*DKq;

    const unsigned s0 = smaddr(smb);
    const unsigned qb = s0;
    const unsigned kb = s0 + 2*Q_H*2;
    const unsigned vb = kb + 2*KV_BUF_H*2;

#pragma unroll
    for (int j = 0; j < 4; j++) {
        int c = t + j*256;
        int row = c >> 3, q = (c & 7)*8;
        unsigned so = (unsigned)(row*72 + q)*2;
        CPASYNC16(qb + so,         Qh + (size_t)(q0+row)*DKq + q);
        CPASYNC16(qb + Q_H*2 + so, Ql + (size_t)(q0+row)*DKq + q);
    }
    load_kv_tile(kb, Kh, Kl, 0, t);
    load_kv_tile(vb, Vh, Vl, 0, t);
    CPCOMMIT;
    CPWAIT0;
    __syncthreads();

    unsigned qfh[4][4], qfl[4][4];
    {
        int arow = warp*16 + (lane & 15);
#pragma unroll
        for (int f = 0; f < 4; f++) {
            unsigned ad = qb + (unsigned)(arow*72 + f*16 + ((lane >> 4) << 3))*2;
            LDSM4(qfh[f][0], qfh[f][1], qfh[f][2], qfh[f][3], ad);
            LDSM4(qfl[f][0], qfl[f][1], qfl[f][2], qfl[f][3], ad + Q_H*2);
        }
    }

    const int g = lane >> 2;
    const int r0 = q0 + warp*16 + g;
    float* aptr0 = attn + ((size_t)bh*Sq + r0)*Sq + 2*(lane & 3);
    float* aptr1 = aptr0 + (size_t)8*Sq;

    float ctx[8][4];
#pragma unroll
    for (int j = 0; j < 8; j++)
#pragma unroll
        for (int r = 0; r < 4; r++) ctx[j][r] = 0.f;

    float l0v = 0.f, l1v = 0.f;
    const int nk = Sq / KT;

    for (int i = 0; i < nk; i++) {
        if (i > 0) { CPWAIT0; __syncthreads(); }
        if (i + 1 < nk) {
            load_kv_tile(kb + ((i+1)&1)*KV_BUF_H*2, Kh, Kl, (i+1)*KT, t);
            load_kv_tile(vb + ((i+1)&1)*KV_BUF_H*2, Vh, Vl, (i+1)*KT, t);
            CPCOMMIT;
        }
        float s[8][4];
        compute_s(s, qfh, qfl, kb + (i&1)*KV_BUF_H*2, lane);

        const int k0 = i*KT;
#pragma unroll
        for (int j = 0; j < 8; j++) {
            float p0 = ex2(s[j][0]);
            float p1 = ex2(s[j][1]);
            float p2 = ex2(s[j][2]);
            float p3 = ex2(s[j][3]);
            *(float2*)(aptr0 + k0 + 8*j) = make_float2(p0, p1);
            *(float2*)(aptr1 + k0 + 8*j) = make_float2(p2, p3);
            l0v += p0 + p1;
            l1v += p2 + p3;
            s[j][0] = p0; s[j][1] = p1; s[j][2] = p2; s[j][3] = p3;
        }

        const unsigned vbuf = vb + (i&1)*KV_BUF_H*2;
#pragma unroll
        for (int f = 0; f < 4; f++) {
            unsigned pah[4], pal[4];
#pragma unroll
            for (int u = 0; u < 2; u++) {
                const float* pv = s[2*f + u];
                unsigned h0 = pack_bf16x2(pv[1], pv[0]);
                float e0 = pv[0] - __uint_as_float(h0 << 16);
                float e1 = pv[1] - __uint_as_float(h0 & 0xffff0000u);
                pal[2*u]   = pack_bf16x2(e1, e0);
                pah[2*u]   = h0;
                unsigned h1 = pack_bf16x2(pv[3], pv[2]);
                float e2 = pv[2] - __uint_as_float(h1 << 16);
                float e3 = pv[3] - __uint_as_float(h1 & 0xffff0000u);
                pal[2*u+1] = pack_bf16x2(e3, e2);
                pah[2*u+1] = h1;
            }
            unsigned pahf[4] = {pah[0], pah[1], pah[2], pah[3]};
            unsigned palf[4] = {pal[0], pal[1], pal[2], pal[3]};

#pragma unroll
            for (int pr = 0; pr < 4; pr++) {
                unsigned off = (unsigned)((f*16 + (lane & 15))*72
                               + pr*16 + ((lane >> 4) << 3))*2;
                unsigned h0,h1,h2,h3, l0,l1,l2,l3;
                LDSM4T(h0,h1,h2,h3, vbuf + off);
                LDSM4T(l0,l1,l2,l3, vbuf + 4608*2 + off);
                unsigned bh0[2]={h0,h1}, bh1[2]={h2,h3};
                unsigned bl0[2]={l0,l1}, bl1[2]={l2,l3};
                MMA16816(ctx[2*pr],   pahf, bh0);
                MMA16816(ctx[2*pr],   pahf, bl0);
                MMA16816(ctx[2*pr],   palf, bh0);
                MMA16816(ctx[2*pr+1], pahf, bh1);
                MMA16816(ctx[2*pr+1], pahf, bl1);
                MMA16816(ctx[2*pr+1], palf, bh1);
            }
        }
        __syncthreads();
    }

    l0v += __shfl_xor_sync(0xffffffffu, l0v, 1);
    l0v += __shfl_xor_sync(0xffffffffu, l0v, 2);
    l1v += __shfl_xor_sync(0xffffffffu, l1v, 1);
    l1v += __shfl_xor_sync(0xffffffffu, l1v, 2);
    const float il0 = 1.0f / l0v;
    const float il1 = 1.0f / l1v;

    if ((lane & 3) == 0) {
        invl[(size_t)bh*Sq + r0]     = il0;
        invl[(size_t)bh*Sq + r0 + 8] = il1;
    }

    const int b = bh >> 4, hidx = bh & 15;
#pragma unroll
    for (int j = 0; j < 8; j++) {
        int d = hidx*DKq + 8*j + 2*(lane & 3);
        size_t idx0 = ((size_t)(b*Sq + r0))*Dm + d;
        split2(ctx[j][0]*il0, ctx[j][1]*il0, ctxh + idx0, ctxl + idx0);
        size_t idx1 = idx0 + (size_t)8*Dm;
        split2(ctx[j][2]*il1, ctx[j][3]*il1, ctxh + idx1, ctxl + idx1);
    }
}

// ---------------------------------------------------------------------------
// fixup: attn[row][:] *= invl[row]
// ---------------------------------------------------------------------------
__global__ __launch_bounds__(256) void fixup_kernel(
    float* __restrict__ attn, const float* __restrict__ invl)
{
    const size_t row = blockIdx.x;
    const float s = invl[row];
    float4* p = (float4*)(attn + row * Sq);
    const int t = threadIdx.x;
    float4 a = p[t], b = p[t + 256];
    a.x *= s; a.y *= s; a.z *= s; a.w *= s;
    b.x *= s; b.y *= s; b.z *= s; b.w *= s;
    p[t] = a;
    p[t + 256] = b;
}

// ---------------------------------------------------------------------------
extern "C" void kernel_launch(void* const* d_in, const int* in_sizes, int n_in,
                              void* d_out, int out_size)
{
    const float* x  = (const float*)d_in[0];
    const float* Wq = (const float*)d_in[1];
    const float* bq = (const float*)d_in[2];
    const float* Wk = (const float*)d_in[3];
    const float* bk = (const float*)d_in[4];
    const float* Wv = (const float*)d_in[5];
    const float* bv = (const float*)d_in[6];
    const float* Wo = (const float*)d_in[7];
    const float* bo = (const float*)d_in[8];

    float* out  = (float*)d_out;
    float* attn = out + (size_t)NROWS * Dm;

    bf16 *xh, *xl, *wh, *wl, *qh, *ql, *kh, *kl, *vh, *vl, *ch, *cl;
    float* invl;
    cudaGetSymbolAddress((void**)&xh, g_xh); cudaGetSymbolAddress((void**)&xl, g_xl);
    cudaGetSymbolAddress((void**)&wh, g_wh); cudaGetSymbolAddress((void**)&wl, g_wl);
    cudaGetSymbolAddress((void**)&qh, g_qh); cudaGetSymbolAddress((void**)&ql, g_ql);
    cudaGetSymbolAddress((void**)&kh, g_kh); cudaGetSymbolAddress((void**)&kl, g_kl);
    cudaGetSymbolAddress((void**)&vh, g_vh); cudaGetSymbolAddress((void**)&vl, g_vl);
    cudaGetSymbolAddress((void**)&ch, g_ch); cudaGetSymbolAddress((void**)&cl, g_cl);
    cudaGetSymbolAddress((void**)&invl, g_invl);

    const int ntSmem = 2 * NT_STAGE_H * 2;           // 81920 B
    const int faSmem = (2*Q_H + 4*KV_BUF_H) * 2;     // 110592 B
    cudaFuncSetAttribute(gemm_bf16x2_nt, cudaFuncAttributeMaxDynamicSharedMemorySize, ntSmem);
    cudaFuncSetAttribute(attn_fused,     cudaFuncAttributeMaxDynamicSharedMemorySize, faSmem);

    // side stream + events (host-side ops, graph-capture safe)
    cudaStream_t s2;
    cudaStreamCreate(&s2);
    cudaEvent_t evF1, evJ1, evF2, evJ2;
    cudaEventCreateWithFlags(&evF1, cudaEventDisableTiming);
    cudaEventCreateWithFlags(&evJ1, cudaEventDisableTiming);
    cudaEventCreateWithFlags(&evF2, cudaEventDisableTiming);
    cudaEventCreateWithFlags(&evJ2, cudaEventDisableTiming);

    // ---- fork 1: W splits (s2) || x split (main) ----
    cudaEventRecord(evF1, 0);
    cudaStreamWaitEvent(s2, evF1, 0);

    const int wq4 = Dm*Dm/4;
    dim3 gW((wq4 + 255)/256, 1, 4);
    wsplit_kernel<<<gW, 256, 0, s2>>>(Wq, Wk, Wv, Wo, wh, wl);
    split_kernel<<<(NROWS*Dm/4 + 255)/256, 256>>>(x, xh, xl, NROWS*Dm/4);

    cudaEventRecord(evJ1, s2);
    cudaStreamWaitEvent(0, evJ1, 0);

    // ---- Q/K/V projections: single fused launch (128x128 tiles, occ 2) ----
    const float QSCALE = 0.18033688011112042f;  // log2(e)/8
    dim3 gQKV(Dm/128, NROWS/128, 3);             // (8, 32, 3) = 768 blocks
    gemm_bf16x2_nt<<<gQKV, 256, ntSmem>>>(xh, xl, wh, wl, bq, bk, bv, QSCALE,
                                          qh, ql, kh, kl, vh, vl, nullptr, 0);

    // ---- fused attention ----
    dim3 gAttn(Sq/128, BH);   // (16, 32)
    attn_fused<<<gAttn, 256, faSmem>>>(qh, ql, kh, kl, vh, vl, attn, invl, ch, cl);

    // ---- fork 2: fixup (s2, DRAM-bound) || O-projection (main, tensor-bound) ----
    cudaEventRecord(evF2, 0);
    cudaStreamWaitEvent(s2, evF2, 0);

    fixup_kernel<<<BH*Sq, 256, 0, s2>>>(attn, invl);

    dim3 gO(Dm/128, NROWS/128, 1);
    gemm_bf16x2_nt<<<gO, 256, ntSmem>>>(ch, cl, wh + (size_t)3*Dm*Dm,
                                        wl + (size_t)3*Dm*Dm,
                                        bo, bo, bo, 1.f,
                                        nullptr, nullptr, nullptr, nullptr,
                                        nullptr, nullptr, out, 1);

    cudaEventRecord(evJ2, s2);
    cudaStreamWaitEvent(0, evJ2, 0);
}

// round 10
// speedup vs baseline: 1.0851x; 1.0552x over previous
#include <cuda_runtime.h>
#include <cuda_bf16.h>

#define Bq 2
#define Sq 2048
#define Dm 1024
#define Hh 16
#define DKq 64
#define NROWS (Bq*Sq)      // 4096
#define BH (Bq*Hh)         // 32

typedef __nv_bfloat16 bf16;

// -------- device scratch (allocation-free rule: __device__ globals) ---------
__device__ bf16 g_xh[NROWS*Dm], g_xl[NROWS*Dm];
__device__ bf16 g_wh[4*Dm*Dm],  g_wl[4*Dm*Dm];
__device__ bf16 g_qh[BH*Sq*DKq], g_ql[BH*Sq*DKq];
__device__ bf16 g_kh[BH*Sq*DKq], g_kl[BH*Sq*DKq];
__device__ bf16 g_vh[BH*Sq*DKq], g_vl[BH*Sq*DKq];
__device__ bf16 g_ch[NROWS*Dm], g_cl[NROWS*Dm];
__device__ float g_invl[BH*Sq];         // per-row 1/sum

// ------------------------------- PTX helpers --------------------------------
#define LDSM4(r0,r1,r2,r3,addr) \
    asm volatile("ldmatrix.sync.aligned.m8n8.x4.shared.b16 {%0,%1,%2,%3},[%4];" \
                 : "=r"(r0),"=r"(r1),"=r"(r2),"=r"(r3) : "r"(addr))
#define LDSM4T(r0,r1,r2,r3,addr) \
    asm volatile("ldmatrix.sync.aligned.m8n8.x4.trans.shared.b16 {%0,%1,%2,%3},[%4];" \
                 : "=r"(r0),"=r"(r1),"=r"(r2),"=r"(r3) : "r"(addr))
#define MMA16816(ac,a,b) \
    asm volatile("mma.sync.aligned.m16n8k16.row.col.f32.bf16.bf16.f32 " \
                 "{%0,%1,%2,%3},{%4,%5,%6,%7},{%8,%9},{%0,%1,%2,%3};" \
                 : "+f"((ac)[0]),"+f"((ac)[1]),"+f"((ac)[2]),"+f"((ac)[3]) \
                 : "r"((a)[0]),"r"((a)[1]),"r"((a)[2]),"r"((a)[3]), \
                   "r"((b)[0]),"r"((b)[1]))
#define CPASYNC16(dst,src) \
    asm volatile("cp.async.cg.shared.global [%0],[%1],16;" \
                 :: "r"(dst), "l"(__cvta_generic_to_global((const void*)(src))))
#define CPCOMMIT asm volatile("cp.async.commit_group;")
#define CPWAIT0  asm volatile("cp.async.wait_group 0;")

__device__ __forceinline__ unsigned smaddr(const void* p) {
    return (unsigned)__cvta_generic_to_shared(p);
}

__device__ __forceinline__ float ex2(float x) {
    float r;
    asm("ex2.approx.f32 %0, %1;" : "=f"(r) : "f"(x));
    return r;
}

__device__ __forceinline__ unsigned pack_bf16x2(float hi, float lo) {
    unsigned r;
    asm("cvt.rn.bf16x2.f32 %0, %1, %2;" : "=r"(r) : "f"(hi), "f"(lo));
    return r;
}

__device__ __forceinline__ void split2(float x, float y, bf16* hp, bf16* lp) {
    unsigned h = pack_bf16x2(y, x);
    float rx = x - __uint_as_float(h << 16);
    float ry = y - __uint_as_float(h & 0xffff0000u);
    unsigned l = pack_bf16x2(ry, rx);
    *(unsigned*)hp = h;
    *(unsigned*)lp = l;
}

// ------------------------------- split kernels ------------------------------
__global__ __launch_bounds__(256) void split_kernel(
    const float* __restrict__ src, bf16* __restrict__ hi, bf16* __restrict__ lo, int n4)
{
    int i = blockIdx.x * blockDim.x + threadIdx.x;
    if (i >= n4) return;
    float4 v = ((const float4*)src)[i];
    split2(v.x, v.y, hi + (size_t)i*4,     lo + (size_t)i*4);
    split2(v.z, v.w, hi + (size_t)i*4 + 2, lo + (size_t)i*4 + 2);
}

__global__ __launch_bounds__(256) void wsplit_kernel(
    const float* __restrict__ w0, const float* __restrict__ w1,
    const float* __restrict__ w2, const float* __restrict__ w3,
    bf16* __restrict__ hi, bf16* __restrict__ lo)
{
    const int z = blockIdx.z;
    const float* src = (z == 0) ? w0 : (z == 1) ? w1 : (z == 2) ? w2 : w3;
    bf16* h = hi + (size_t)z * Dm * Dm;
    bf16* l = lo + (size_t)z * Dm * Dm;
    int i = blockIdx.x * blockDim.x + threadIdx.x;
    if (i >= Dm*Dm/4) return;
    float4 v = ((const float4*)src)[i];
    split2(v.x, v.y, h + (size_t)i*4,     l + (size_t)i*4);
    split2(v.z, v.w, h + (size_t)i*4 + 2, l + (size_t)i*4 + 2);
}

// ---------------------------------------------------------------------------
// NT GEMM on hi/lo bf16 pairs: 128x128 block, 256 threads, 8 warps (2m x 4n),
// warp tile 64x32, K-tile 32, double-buffered cp.async. occupancy 2.
// ---------------------------------------------------------------------------
#define NT_STAGE_H 20480   // halves per stage: 4 matrices * 128*40

__device__ __forceinline__ void nt_load(
    unsigned sb,
    const bf16* __restrict__ Ah, const bf16* __restrict__ Al,
    const bf16* __restrict__ Wh, const bf16* __restrict__ Wl,
    int m0, int n0, int kt, int t)
{
#pragma unroll
    for (int j = 0; j < 2; j++) {
        int idx = t + j*256;
        int row = idx >> 2;
        int q   = (idx & 3) * 8;
        unsigned so = (unsigned)(row*40 + q) * 2;
        CPASYNC16(sb + so,               Ah + (size_t)(m0+row)*Dm + kt + q);
        CPASYNC16(sb + 5120*2  + so,     Al + (size_t)(m0+row)*Dm + kt + q);
        CPASYNC16(sb + 10240*2 + so,     Wh + (size_t)(n0+row)*Dm + kt + q);
        CPASYNC16(sb + 15360*2 + so,     Wl + (size_t)(n0+row)*Dm + kt + q);
    }
}

__global__ __launch_bounds__(256, 2) void gemm_bf16x2_nt(
    const bf16* __restrict__ Ah, const bf16* __restrict__ Al,
    const bf16* __restrict__ WhB, const bf16* __restrict__ WlB,
    const float* __restrict__ b0, const float* __restrict__ b1,
    const float* __restrict__ b2, float qscale,
    bf16* __restrict__ o0h, bf16* __restrict__ o0l,
    bf16* __restrict__ o1h, bf16* __restrict__ o1l,
    bf16* __restrict__ o2h, bf16* __restrict__ o2l,
    float* __restrict__ outF, int mode)
{
    extern __shared__ bf16 sm[];
    const int t    = threadIdx.x;
    const int lane = t & 31;
    const int wid  = t >> 5;
    const int warp_m = wid >> 2;
    const int warp_n = wid & 3;
    const int m0 = blockIdx.y * 128;
    const int n0 = blockIdx.x * 128;
    const int z  = blockIdx.z;

    const bf16* Wh = WhB + (size_t)z * Dm * Dm;
    const bf16* Wl = WlB + (size_t)z * Dm * Dm;
    const float* bias = (z == 0) ? b0 : (z == 1 ? b1 : b2);
    const float scale = (mode == 0 && z == 0) ? qscale : 1.f;

    float acc[4][4][4];
#pragma unroll
    for (int i = 0; i < 4; i++)
#pragma unroll
        for (int j = 0; j < 4; j++)
#pragma unroll
            for (int r = 0; r < 4; r++) acc[i][j][r] = 0.f;

    const unsigned s0 = smaddr(sm);
    const int nk = Dm / 32;

    nt_load(s0, Ah, Al, Wh, Wl, m0, n0, 0, t);
    CPCOMMIT;

    for (int i = 0; i < nk; i++) {
        CPWAIT0;
        __syncthreads();
        if (i + 1 < nk) {
            nt_load(s0 + ((i+1)&1)*NT_STAGE_H*2, Ah, Al, Wh, Wl,
                    m0, n0, (i+1)*32, t);
            CPCOMMIT;
        }
        unsigned sb = s0 + (i&1)*NT_STAGE_H*2;

#pragma unroll
        for (int k16 = 0; k16 < 32; k16 += 16) {
            unsigned ah[4][4], al[4][4], bh[4][2], bl[4][2];
            int arow = warp_m*64 + (lane & 15);
            int acol = k16 + ((lane >> 4) << 3);
#pragma unroll
            for (int mt = 0; mt < 4; mt++) {
                unsigned ad = sb + (unsigned)((arow + mt*16)*40 + acol)*2;
                LDSM4(ah[mt][0], ah[mt][1], ah[mt][2], ah[mt][3], ad);
                LDSM4(al[mt][0], al[mt][1], al[mt][2], al[mt][3], ad + 5120*2);
            }
            int brow = warp_n*32 + ((lane >> 4) << 3) + (lane & 7);
            int bcol = k16 + (((lane >> 3) & 1) << 3);
#pragma unroll
            for (int pr = 0; pr < 2; pr++) {
                unsigned bd = sb + 10240*2 + (unsigned)((brow + pr*16)*40 + bcol)*2;
                unsigned r0, r1, r2, r3;
                LDSM4(r0, r1, r2, r3, bd);
                bh[pr*2][0] = r0; bh[pr*2][1] = r1;
                bh[pr*2+1][0] = r2; bh[pr*2+1][1] = r3;
                LDSM4(r0, r1, r2, r3, bd + 5120*2);
                bl[pr*2][0] = r0; bl[pr*2][1] = r1;
                bl[pr*2+1][0] = r2; bl[pr*2+1][1] = r3;
            }
#pragma unroll
            for (int mt = 0; mt < 4; mt++)
#pragma unroll
                for (int nt = 0; nt < 4; nt++) {
                    MMA16816(acc[mt][nt], ah[mt], bh[nt]);
                    MMA16816(acc[mt][nt], ah[mt], bl[nt]);
                    MMA16816(acc[mt][nt], al[mt], bh[nt]);
                }
        }
    }

#pragma unroll
    for (int mt = 0; mt < 4; mt++)
#pragma unroll
        for (int nt = 0; nt < 4; nt++) {
            int r = m0 + warp_m*64 + mt*16 + (lane >> 2);
            int c = n0 + warp_n*32 + nt*8 + ((lane & 3) << 1);
            float v00 = acc[mt][nt][0] + bias[c];
            float v01 = acc[mt][nt][1] + bias[c+1];
            float v10 = acc[mt][nt][2] + bias[c];
            float v11 = acc[mt][nt][3] + bias[c+1];
            if (mode == 1) {
                *(float2*)&outF[(size_t)r*Dm + c]     = make_float2(v00, v01);
                *(float2*)&outF[(size_t)(r+8)*Dm + c] = make_float2(v10, v11);
            } else {
                v00 *= scale; v01 *= scale; v10 *= scale; v11 *= scale;
                bf16* ohp = (z == 0) ? o0h : (z == 1 ? o1h : o2h);
                bf16* olp = (z == 0) ? o0l : (z == 1 ? o1l : o2l);
                int b = r >> 11, s = r & 2047;
                int h = c >> 6,  dk = c & 63;
                size_t base = (((size_t)(b*Hh + h))*Sq + s)*DKq + dk;
                split2(v00, v01, ohp + base, olp + base);
                split2(v10, v11, ohp + base + 8*DKq, olp + base + 8*DKq);
            }
        }
}

// ---------------------------------------------------------------------------
// Fused attention, occupancy-2 version: KT=32, Q frags reloaded from smem.
// Block: 128 q-rows, 8 warps x 16 rows. regs target <=128 (2 CTAs/SM).
// ---------------------------------------------------------------------------
#define KT 32
#define KV_BUF_H 4608      // halves per K (or V) buffer: hi(2304)+lo(2304)
#define Q_H 9216           // halves per Q matrix (128*72)

__device__ __forceinline__ void load_kv_tile(
    unsigned dsth, const bf16* __restrict__ gh, const bf16* __restrict__ gl,
    int row0, int t)
{
    int row = t >> 3;            // 0..31
    int q   = (t & 7) * 8;       // 0..56
    unsigned so = (unsigned)(row*72 + q)*2;
    CPASYNC16(dsth + so,          gh + (size_t)(row0+row)*DKq + q);
    CPASYNC16(dsth + 2304*2 + so, gl + (size_t)(row0+row)*DKq + q);
}

// S tile: warp computes 16 q-rows x 32 k-cols. Q frags loaded from smem.
__device__ __forceinline__ void compute_s(
    float s[4][4], unsigned qrow_ad, unsigned kbuf, int lane)
{
#pragma unroll
    for (int j = 0; j < 4; j++)
#pragma unroll
        for (int r = 0; r < 4; r++) s[j][r] = 0.f;

    const int rbase = ((lane >> 4) << 3) + (lane & 7);
#pragma unroll
    for (int f = 0; f < 4; f++) {
        unsigned qh[4], ql[4];
        unsigned ad = qrow_ad + (unsigned)(f*16)*2;
        LDSM4(qh[0], qh[1], qh[2], qh[3], ad);
        LDSM4(ql[0], ql[1], ql[2], ql[3], ad + Q_H*2);
        const int cbase = f*16 + (((lane >> 3) & 1) << 3);
#pragma unroll
        for (int pr = 0; pr < 2; pr++) {
            unsigned off = (unsigned)((pr*16 + rbase)*72 + cbase)*2;
            unsigned h0,h1,h2,h3, l0,l1,l2,l3;
            LDSM4(h0,h1,h2,h3, kbuf + off);
            LDSM4(l0,l1,l2,l3, kbuf + 2304*2 + off);
            unsigned bh0[2]={h0,h1}, bh1[2]={h2,h3};
            unsigned bl0[2]={l0,l1}, bl1[2]={l2,l3};
            MMA16816(s[2*pr],   qh, bh0);
            MMA16816(s[2*pr],   qh, bl0);
            MMA16816(s[2*pr],   ql, bh0);
            MMA16816(s[2*pr+1], qh, bh1);
            MMA16816(s[2*pr+1], qh, bl1);
            MMA16816(s[2*pr+1], ql, bh1);
        }
    }
}

__global__ __launch_bounds__(256, 2) void attn_fused(
    const bf16* __restrict__ qh_g, const bf16* __restrict__ ql_g,
    const bf16* __restrict__ kh_g, const bf16* __restrict__ kl_g,
    const bf16* __restrict__ vh_g, const bf16* __restrict__ vl_g,
    float* __restrict__ attn, float* __restrict__ invl,
    bf16* __restrict__ ctxh, bf16* __restrict__ ctxl)
{
    extern __shared__ bf16 smb[];
    const int t = threadIdx.x, lane = t & 31, warp = t >> 5;
    const int bh = blockIdx.y, q0 = blockIdx.x * 128;
    const bf16* Qh = qh_g + (size_t)bh*Sq*DKq;
    const bf16* Ql = ql_g + (size_t)bh*Sq*DKq;
    const bf16* Kh = kh_g + (size_t)bh*Sq*DKq;
    const bf16* Kl = kl_g + (size_t)bh*Sq*DKq;
    const bf16* Vh = vh_g + (size_t)bh*Sq*DKq;
    const bf16* Vl = vl_g + (size_t)bh*Sq*DKq;

    const unsigned s0 = smaddr(smb);
    const unsigned qb = s0;
    const unsigned kb = s0 + 2*Q_H*2;
    const unsigned vb = kb + 2*KV_BUF_H*2;

#pragma unroll
    for (int j = 0; j < 4; j++) {
        int c = t + j*256;
        int row = c >> 3, q = (c & 7)*8;
        unsigned so = (unsigned)(row*72 + q)*2;
        CPASYNC16(qb + so,         Qh + (size_t)(q0+row)*DKq + q);
        CPASYNC16(qb + Q_H*2 + so, Ql + (size_t)(q0+row)*DKq + q);
    }
    load_kv_tile(kb, Kh, Kl, 0, t);
    load_kv_tile(vb, Vh, Vl, 0, t);
    CPCOMMIT;
    CPWAIT0;
    __syncthreads();

    // per-warp Q fragment smem row base (A-operand ldmatrix address w/o f-offset)
    const unsigned qrow_ad = qb +
        (unsigned)((warp*16 + (lane & 15))*72 + ((lane >> 4) << 3))*2;

    const int g = lane >> 2;
    const int r0 = q0 + warp*16 + g;
    float* aptr0 = attn + ((size_t)bh*Sq + r0)*Sq + 2*(lane & 3);
    float* aptr1 = aptr0 + (size_t)8*Sq;

    float ctx[8][4];
#pragma unroll
    for (int j = 0; j < 8; j++)
#pragma unroll
        for (int r = 0; r < 4; r++) ctx[j][r] = 0.f;

    float l0v = 0.f, l1v = 0.f;
    const int nk = Sq / KT;    // 64

    for (int i = 0; i < nk; i++) {
        if (i > 0) { CPWAIT0; __syncthreads(); }
        if (i + 1 < nk) {
            load_kv_tile(kb + ((i+1)&1)*KV_BUF_H*2, Kh, Kl, (i+1)*KT, t);
            load_kv_tile(vb + ((i+1)&1)*KV_BUF_H*2, Vh, Vl, (i+1)*KT, t);
            CPCOMMIT;
        }
        float s[4][4];
        compute_s(s, qrow_ad, kb + (i&1)*KV_BUF_H*2, lane);

        const int k0 = i*KT;
#pragma unroll
        for (int j = 0; j < 4; j++) {
            float p0 = ex2(s[j][0]);
            float p1 = ex2(s[j][1]);
            float p2 = ex2(s[j][2]);
            float p3 = ex2(s[j][3]);
            *(float2*)(aptr0 + k0 + 8*j) = make_float2(p0, p1);
            *(float2*)(aptr1 + k0 + 8*j) = make_float2(p2, p3);
            l0v += p0 + p1;
            l1v += p2 + p3;
            s[j][0] = p0; s[j][1] = p1; s[j][2] = p2; s[j][3] = p3;
        }

        // PV: A-fragments from p registers (hi + residual lo), V via ldsm.trans
        const unsigned vbuf = vb + (i&1)*KV_BUF_H*2;
#pragma unroll
        for (int f = 0; f < 2; f++) {
            unsigned pah[4], pal[4];
#pragma unroll
            for (int u = 0; u < 2; u++) {
                const float* pv = s[2*f + u];
                unsigned h0 = pack_bf16x2(pv[1], pv[0]);
                float e0 = pv[0] - __uint_as_float(h0 << 16);
                float e1 = pv[1] - __uint_as_float(h0 & 0xffff0000u);
                pal[2*u]   = pack_bf16x2(e1, e0);
                pah[2*u]   = h0;
                unsigned h1 = pack_bf16x2(pv[3], pv[2]);
                float e2 = pv[2] - __uint_as_float(h1 << 16);
                float e3 = pv[3] - __uint_as_float(h1 & 0xffff0000u);
                pal[2*u+1] = pack_bf16x2(e3, e2);
                pah[2*u+1] = h1;
            }

#pragma unroll
            for (int pr = 0; pr < 4; pr++) {
                unsigned off = (unsigned)((f*16 + (lane & 15))*72
                               + pr*16 + ((lane >> 4) << 3))*2;
                unsigned h0,h1,h2,h3, l0,l1,l2,l3;
                LDSM4T(h0,h1,h2,h3, vbuf + off);
                LDSM4T(l0,l1,l2,l3, vbuf + 2304*2 + off);
                unsigned bh0[2]={h0,h1}, bh1[2]={h2,h3};
                unsigned bl0[2]={l0,l1}, bl1[2]={l2,l3};
                MMA16816(ctx[2*pr],   pah, bh0);
                MMA16816(ctx[2*pr],   pah, bl0);
                MMA16816(ctx[2*pr],   pal, bh0);
                MMA16816(ctx[2*pr+1], pah, bh1);
                MMA16816(ctx[2*pr+1], pah, bl1);
                MMA16816(ctx[2*pr+1], pal, bh1);
            }
        }
        __syncthreads();
    }

    l0v += __shfl_xor_sync(0xffffffffu, l0v, 1);
    l0v += __shfl_xor_sync(0xffffffffu, l0v, 2);
    l1v += __shfl_xor_sync(0xffffffffu, l1v, 1);
    l1v += __shfl_xor_sync(0xffffffffu, l1v, 2);
    const float il0 = 1.0f / l0v;
    const float il1 = 1.0f / l1v;

    if ((lane & 3) == 0) {
        invl[(size_t)bh*Sq + r0]     = il0;
        invl[(size_t)bh*Sq + r0 + 8] = il1;
    }

    const int b = bh >> 4, hidx = bh & 15;
#pragma unroll
    for (int j = 0; j < 8; j++) {
        int d = hidx*DKq + 8*j + 2*(lane & 3);
        size_t idx0 = ((size_t)(b*Sq + r0))*Dm + d;
        split2(ctx[j][0]*il0, ctx[j][1]*il0, ctxh + idx0, ctxl + idx0);
        size_t idx1 = idx0 + (size_t)8*Dm;
        split2(ctx[j][2]*il1, ctx[j][3]*il1, ctxh + idx1, ctxl + idx1);
    }
}

// ---------------------------------------------------------------------------
// fixup: attn[row][:] *= invl[row]
// ---------------------------------------------------------------------------
__global__ __launch_bounds__(256) void fixup_kernel(
    float* __restrict__ attn, const float* __restrict__ invl)
{
    const size_t row = blockIdx.x;
    const float s = invl[row];
    float4* p = (float4*)(attn + row * Sq);
    const int t = threadIdx.x;
    float4 a = p[t], b = p[t + 256];
    a.x *= s; a.y *= s; a.z *= s; a.w *= s;
    b.x *= s; b.y *= s; b.z *= s; b.w *= s;
    p[t] = a;
    p[t + 256] = b;
}

// ---------------------------------------------------------------------------
extern "C" void kernel_launch(void* const* d_in, const int* in_sizes, int n_in,
                              void* d_out, int out_size)
{
    const float* x  = (const float*)d_in[0];
    const float* Wq = (const float*)d_in[1];
    const float* bq = (const float*)d_in[2];
    const float* Wk = (const float*)d_in[3];
    const float* bk = (const float*)d_in[4];
    const float* Wv = (const float*)d_in[5];
    const float* bv = (const float*)d_in[6];
    const float* Wo = (const float*)d_in[7];
    const float* bo = (const float*)d_in[8];

    float* out  = (float*)d_out;
    float* attn = out + (size_t)NROWS * Dm;

    bf16 *xh, *xl, *wh, *wl, *qh, *ql, *kh, *kl, *vh, *vl, *ch, *cl;
    float* invl;
    cudaGetSymbolAddress((void**)&xh, g_xh); cudaGetSymbolAddress((void**)&xl, g_xl);
    cudaGetSymbolAddress((void**)&wh, g_wh); cudaGetSymbolAddress((void**)&wl, g_wl);
    cudaGetSymbolAddress((void**)&qh, g_qh); cudaGetSymbolAddress((void**)&ql, g_ql);
    cudaGetSymbolAddress((void**)&kh, g_kh); cudaGetSymbolAddress((void**)&kl, g_kl);
    cudaGetSymbolAddress((void**)&vh, g_vh); cudaGetSymbolAddress((void**)&vl, g_vl);
    cudaGetSymbolAddress((void**)&ch, g_ch); cudaGetSymbolAddress((void**)&cl, g_cl);
    cudaGetSymbolAddress((void**)&invl, g_invl);

    const int ntSmem = 2 * NT_STAGE_H * 2;           // 81920 B
    const int faSmem = (2*Q_H + 4*KV_BUF_H) * 2;     // 73728 B
    cudaFuncSetAttribute(gemm_bf16x2_nt, cudaFuncAttributeMaxDynamicSharedMemorySize, ntSmem);
    cudaFuncSetAttribute(attn_fused,     cudaFuncAttributeMaxDynamicSharedMemorySize, faSmem);

    // side stream + events (host-side ops, graph-capture safe)
    cudaStream_t s2;
    cudaStreamCreate(&s2);
    cudaEvent_t evF1, evJ1, evF2, evJ2;
    cudaEventCreateWithFlags(&evF1, cudaEventDisableTiming);
    cudaEventCreateWithFlags(&evJ1, cudaEventDisableTiming);
    cudaEventCreateWithFlags(&evF2, cudaEventDisableTiming);
    cudaEventCreateWithFlags(&evJ2, cudaEventDisableTiming);

    // ---- fork 1: W splits (s2) || x split (main) ----
    cudaEventRecord(evF1, 0);
    cudaStreamWaitEvent(s2, evF1, 0);

    const int wq4 = Dm*Dm/4;
    dim3 gW((wq4 + 255)/256, 1, 4);
    wsplit_kernel<<<gW, 256, 0, s2>>>(Wq, Wk, Wv, Wo, wh, wl);
    split_kernel<<<(NROWS*Dm/4 + 255)/256, 256>>>(x, xh, xl, NROWS*Dm/4);

    cudaEventRecord(evJ1, s2);
    cudaStreamWaitEvent(0, evJ1, 0);

    // ---- Q/K/V projections: single fused launch (128x128 tiles, occ 2) ----
    const float QSCALE = 0.18033688011112042f;  // log2(e)/8
    dim3 gQKV(Dm/128, NROWS/128, 3);             // (8, 32, 3) = 768 blocks
    gemm_bf16x2_nt<<<gQKV, 256, ntSmem>>>(xh, xl, wh, wl, bq, bk, bv, QSCALE,
                                          qh, ql, kh, kl, vh, vl, nullptr, 0);

    // ---- fused attention (occ 2) ----
    dim3 gAttn(Sq/128, BH);   // (16, 32)
    attn_fused<<<gAttn, 256, faSmem>>>(qh, ql, kh, kl, vh, vl, attn, invl, ch, cl);

    // ---- fork 2: fixup (s2, DRAM-bound) || O-projection (main, tensor-bound) ----
    cudaEventRecord(evF2, 0);
    cudaStreamWaitEvent(s2, evF2, 0);

    fixup_kernel<<<BH*Sq, 256, 0, s2>>>(attn, invl);

    dim3 gO(Dm/128, NROWS/128, 1);
    gemm_bf16x2_nt<<<gO, 256, ntSmem>>>(ch, cl, wh + (size_t)3*Dm*Dm,
                                        wl + (size_t)3*Dm*Dm,
                                        bo, bo, bo, 1.f,
                                        nullptr, nullptr, nullptr, nullptr,
                                        nullptr, nullptr, out, 1);

    cudaEventRecord(evJ2, s2);
    cudaStreamWaitEvent(0, evJ2, 0);
}